// round 2
// baseline (speedup 1.0000x reference)
#include <cuda_runtime.h>
#include <math.h>

#define BB 512
#define TT 192
#define CC 256

// ---------------- scratch (device globals; no allocation) ----------------
__device__ float g_conv[(size_t)BB * CC * TT];   // conv output   [B,256,192]
__device__ float g_xbuf[(size_t)BB * CC * TT];   // interp output [B,256,192]
__device__ float g_xg[(size_t)2 * BB * TT * 128];// lstm pre-gates [dir,B,T,128]
__device__ float g_mu[BB * 16];
__device__ float g_rsig[BB * 16];
__device__ int   g_gi[BB * TT];
__device__ float g_lam[BB * TT];

// ---------------- threefry2x32 (JAX), host + device ----------------
__host__ __device__ __forceinline__ void tf2x32(unsigned k0, unsigned k1,
                                                unsigned x0, unsigned x1,
                                                unsigned& y0, unsigned& y1) {
  unsigned ks2 = k0 ^ k1 ^ 0x1BD11BDAu;
  x0 += k0; x1 += k1;
#define TFR(r) x0 += x1; x1 = (x1 << (r)) | (x1 >> (32 - (r))); x1 ^= x0;
  TFR(13) TFR(15) TFR(26) TFR(6)
  x0 += k1;  x1 += ks2 + 1u;
  TFR(17) TFR(29) TFR(16) TFR(24)
  x0 += ks2; x1 += k0 + 2u;
  TFR(13) TFR(15) TFR(26) TFR(6)
  x0 += k0;  x1 += k1 + 3u;
  TFR(17) TFR(29) TFR(16) TFR(24)
  x0 += k1;  x1 += ks2 + 4u;
  TFR(13) TFR(15) TFR(26) TFR(6)
  x0 += ks2; x1 += k0 + 5u;
#undef TFR
  y0 = x0; y1 = x1;
}

__device__ __forceinline__ unsigned tf_bits32(unsigned k0, unsigned k1, unsigned n) {
  unsigned y0, y1;
  tf2x32(k0, k1, 0u, n, y0, y1);
  return y0 ^ y1;   // jax partitionable random_bits (32-bit)
}

// ---------------- conv1d K=5 'same', implicit GEMM ----------------
// tile: 128 outputs x 64 t per 256-thread block; thread: 8 o (stride16) x 4 t.
#define CICH 8
__global__ __launch_bounds__(256) void conv_kernel(
    const float* __restrict__ x, const float* __restrict__ w,
    const float* __restrict__ bias, float* __restrict__ out, int Cin) {
  __shared__ float xs[CICH][68];
  __shared__ float ws[CICH][5][128];
  int b = blockIdx.z;
  int obase = blockIdx.y * 128;
  int tbase = blockIdx.x * 64;
  int tid = threadIdx.x;
  int otid = tid & 15;
  int ttid = tid >> 4;
  float acc[8][4];
#pragma unroll
  for (int u = 0; u < 8; u++)
#pragma unroll
    for (int v = 0; v < 4; v++) acc[u][v] = 0.f;
  const float* xb = x + (size_t)b * Cin * TT;
  int wstride = Cin * 5;
  for (int ci0 = 0; ci0 < Cin; ci0 += CICH) {
    for (int idx = tid; idx < CICH * 68; idx += 256) {
      int i = idx / 68, j = idx - i * 68;
      int ci = ci0 + i, t = tbase + j - 2;
      xs[i][j] = (ci < Cin && t >= 0 && t < TT) ? xb[(size_t)ci * TT + t] : 0.f;
    }
    for (int idx = tid; idx < CICH * 5 * 128; idx += 256) {
      int o = idx / 40, r = idx - o * 40;
      int i = r / 5, k = r - i * 5;
      int ci = ci0 + i;
      ws[i][k][o] = (ci < Cin) ? w[(size_t)(obase + o) * wstride + ci * 5 + k] : 0.f;
    }
    __syncthreads();
#pragma unroll
    for (int i = 0; i < CICH; i++) {
      float xv[8];
#pragma unroll
      for (int j = 0; j < 8; j++) xv[j] = xs[i][ttid * 4 + j];
#pragma unroll
      for (int u = 0; u < 8; u++) {
#pragma unroll
        for (int k = 0; k < 5; k++) {
          float wv = ws[i][k][otid + 16 * u];
#pragma unroll
          for (int v = 0; v < 4; v++) acc[u][v] = fmaf(wv, xv[v + k], acc[u][v]);
        }
      }
    }
    __syncthreads();
  }
#pragma unroll
  for (int u = 0; u < 8; u++) {
    int o = obase + otid + 16 * u;
    float bv = bias[o];
    float4 r4;
    r4.x = acc[u][0] + bv; r4.y = acc[u][1] + bv;
    r4.z = acc[u][2] + bv; r4.w = acc[u][3] + bv;
    *reinterpret_cast<float4*>(out + ((size_t)b * CC + o) * TT + tbase + ttid * 4) = r4;
  }
}

// ---------------- GroupNorm stats: one block per (b, group) ----------------
__global__ __launch_bounds__(128) void gn_stats(const float* __restrict__ conv,
                                                float* __restrict__ mu,
                                                float* __restrict__ rsig) {
  __shared__ float ss[128], ss2[128];
  int b = blockIdx.x >> 4, g = blockIdx.x & 15;
  const float* p = conv + ((size_t)b * CC + g * 16) * TT;
  float s = 0.f, s2 = 0.f;
  for (int i = threadIdx.x; i < 16 * TT; i += 128) {
    float v = p[i];
    s += v;
    s2 = fmaf(v, v, s2);
  }
  ss[threadIdx.x] = s; ss2[threadIdx.x] = s2;
  __syncthreads();
  for (int off = 64; off > 0; off >>= 1) {
    if (threadIdx.x < off) {
      ss[threadIdx.x] += ss[threadIdx.x + off];
      ss2[threadIdx.x] += ss2[threadIdx.x + off];
    }
    __syncthreads();
  }
  if (threadIdx.x == 0) {
    float m = ss[0] * (1.0f / 3072.0f);
    float var = ss2[0] * (1.0f / 3072.0f) - m * m;
    mu[blockIdx.x] = m;
    rsig[blockIdx.x] = rsqrtf(var + 1e-5f);
  }
}

// ---------------- interp_lnr metadata: one thread per batch ----------------
__global__ void interp_meta(int* __restrict__ gi, float* __restrict__ lam,
                            unsigned u0, unsigned u1, unsigned a0, unsigned a1,
                            unsigned c0, unsigned c1) {
  int b = blockIdx.x * blockDim.x + threadIdx.x;
  if (b >= BB) return;
  int base = b * TT;
  for (int t = 0; t < TT; t++) gi[base + t] = -1;
  int off = 0, pos = 0;
  for (int s = 0; s < 7; s++) {
    unsigned n = (unsigned)(b * 7 + s);
    unsigned ub = tf_bits32(u0, u1, n);
    float f = __uint_as_float((ub >> 9) | 0x3f800000u) - 1.0f;  // [0,1)
    float scale = f + 0.5f;
    unsigned hb = tf_bits32(a0, a1, n);
    unsigned lb = tf_bits32(c0, c1, n);
    unsigned offt = ((hb % 13u) * 9u + lb % 13u) % 13u;  // 2^32 % 13 == 9
    int len = 19 + (int)offt;
    float lenm1 = (float)(len - 1);
    for (int l = 0; l < 64; l++) {
      float idx = __fdiv_rn((float)l, scale);
      float fl = floorf(idx);
      float lm = idx - fl;
      if (fl < lenm1) {
        int io = (int)fl + off;
        if (io < TT - 1) {
          if (pos < TT) { gi[base + pos] = io; lam[base + pos] = lm; }
          pos++;
        }
      }
    }
    off += len;
  }
}

// ---------------- interp apply: fused GN norm + ReLU + lerp gather ----------------
__global__ __launch_bounds__(192) void interp_apply(
    const float* __restrict__ conv, const int* __restrict__ gi,
    const float* __restrict__ lam, const float* __restrict__ mu,
    const float* __restrict__ rsig, const float* __restrict__ gnw,
    const float* __restrict__ gnb, float* __restrict__ out) {
  int b = blockIdx.x, t = threadIdx.x;
  __shared__ float smu[16], srs[16];
  __shared__ int sg[TT];
  __shared__ float sl[TT];
  if (t < 16) { smu[t] = mu[b * 16 + t]; srs[t] = rsig[b * 16 + t]; }
  sg[t] = gi[b * TT + t];
  sl[t] = lam[b * TT + t];
  __syncthreads();
  int g = sg[t];
  float lm = sl[t];
  const float* cb = conv + (size_t)b * CC * TT;
  float* ob = out + (size_t)b * CC * TT;
  for (int c = 0; c < CC; c++) {
    float val = 0.f;
    if (g >= 0) {
      float m = smu[c >> 4], rs = srs[c >> 4];
      float w = gnw[c], be = gnb[c];
      float a = cb[c * TT + g], e = cb[c * TT + g + 1];
      float fa = fmaxf((a - m) * rs * w + be, 0.f);
      float fb = fmaxf((e - m) * rs * w + be, 0.f);
      val = (1.0f - lm) * fa + lm * fb;
    }
    ob[c * TT + t] = val;
  }
}

// ---------------- xg pre-gate GEMM: [dir,B,T,128] ----------------
__global__ __launch_bounds__(256) void xg_gemm(
    const float* __restrict__ x, const float* __restrict__ wf,
    const float* __restrict__ wb, const float* __restrict__ bif,
    const float* __restrict__ bhf, const float* __restrict__ bib,
    const float* __restrict__ bhb, float* __restrict__ xg) {
  __shared__ float xs[8][64];
  __shared__ float ws[8][128];
  int d = blockIdx.y, b = blockIdx.z, tbase = blockIdx.x * 64;
  const float* w = d ? wb : wf;
  const float* bi = d ? bib : bif;
  const float* bh = d ? bhb : bhf;
  int tid = threadIdx.x, otid = tid & 15, ttid = tid >> 4;
  float acc[8][4];
#pragma unroll
  for (int u = 0; u < 8; u++)
#pragma unroll
    for (int v = 0; v < 4; v++) acc[u][v] = 0.f;
  const float* xb = x + (size_t)b * CC * TT;
  for (int ci0 = 0; ci0 < CC; ci0 += 8) {
    for (int idx = tid; idx < 512; idx += 256) {
      int i = idx >> 6, j = idx & 63;
      xs[i][j] = xb[(size_t)(ci0 + i) * TT + tbase + j];
    }
    for (int idx = tid; idx < 1024; idx += 256) {
      int o = idx >> 3, i = idx & 7;
      ws[i][o] = w[(size_t)o * CC + ci0 + i];
    }
    __syncthreads();
#pragma unroll
    for (int i = 0; i < 8; i++) {
      float xv[4];
#pragma unroll
      for (int v = 0; v < 4; v++) xv[v] = xs[i][ttid * 4 + v];
#pragma unroll
      for (int u = 0; u < 8; u++) {
        float wv = ws[i][otid + 16 * u];
#pragma unroll
        for (int v = 0; v < 4; v++) acc[u][v] = fmaf(wv, xv[v], acc[u][v]);
      }
    }
    __syncthreads();
  }
#pragma unroll
  for (int u = 0; u < 8; u++) {
    int g = otid + 16 * u;
    float bias = bi[g] + bh[g];
#pragma unroll
    for (int v = 0; v < 4; v++) {
      int t = tbase + ttid * 4 + v;
      xg[((size_t)(d * BB + b) * TT + t) * 128 + g] = acc[u][v] + bias;
    }
  }
}

// ---------------- LSTM recurrence: warp per batch element ----------------
__device__ __forceinline__ float sigf(float x) { return 1.0f / (1.0f + expf(-x)); }

__global__ __launch_bounds__(256) void lstm_kernel(
    const float* __restrict__ xg, const float* __restrict__ whf,
    const float* __restrict__ whb, float* __restrict__ out) {
  __shared__ float ws[32 * 128];  // ws[j*128 + row]
  int dir = blockIdx.y;
  const float* wh = dir ? whb : whf;
  int tid = threadIdx.x;
  for (int idx = tid; idx < 4096; idx += 256) {
    int j = idx >> 7, r = idx & 127;
    ws[idx] = wh[r * 32 + j];
  }
  __syncthreads();
  int warp = tid >> 5, lane = tid & 31;
  int b = blockIdx.x * 8 + warp;
  const float* xgb = xg + (size_t)(dir * BB + b) * TT * 128;
  float h = 0.f, c = 0.f;
  for (int step = 0; step < TT; step++) {
    int t = dir ? (TT - 1 - step) : step;
    const float* p = xgb + (size_t)t * 128;
    float gi = p[lane], gf = p[32 + lane], gg = p[64 + lane], go = p[96 + lane];
#pragma unroll
    for (int j = 0; j < 32; j++) {
      float hj = __shfl_sync(0xffffffffu, h, j);
      const float* wr = ws + j * 128;
      gi = fmaf(wr[lane], hj, gi);
      gf = fmaf(wr[32 + lane], hj, gf);
      gg = fmaf(wr[64 + lane], hj, gg);
      go = fmaf(wr[96 + lane], hj, go);
    }
    c = sigf(gf) * c + sigf(gi) * tanhf(gg);
    h = sigf(go) * tanhf(c);
    if (dir == 0) {
      if ((t & 7) == 7) out[((size_t)b * 24 + (t >> 3)) * 64 + lane] = h;
    } else {
      if ((t & 7) == 0) out[((size_t)b * 24 + (t >> 3)) * 64 + 32 + lane] = h;
    }
  }
}

// ---------------- launch ----------------
extern "C" void kernel_launch(void* const* d_in, const int* in_sizes, int n_in,
                              void* d_out, int out_size) {
  (void)in_sizes; (void)n_in;
  float *p_conv, *p_xbuf, *p_xg, *p_mu, *p_rsig, *p_lam;
  int* p_gi;
  cudaGetSymbolAddress((void**)&p_conv, g_conv);
  cudaGetSymbolAddress((void**)&p_xbuf, g_xbuf);
  cudaGetSymbolAddress((void**)&p_xg, g_xg);
  cudaGetSymbolAddress((void**)&p_mu, g_mu);
  cudaGetSymbolAddress((void**)&p_rsig, g_rsig);
  cudaGetSymbolAddress((void**)&p_gi, g_gi);
  cudaGetSymbolAddress((void**)&p_lam, g_lam);

  const float* x0 = (const float*)d_in[0];

  // JAX threefry keys: rng = key(42); per layer i: fold_in -> split -> randint split
  unsigned keys[3][6];
  for (int i = 0; i < 3; i++) {
    unsigned f0, f1;
    tf2x32(0u, 42u, 0u, (unsigned)i, f0, f1);         // fold_in(key, i)
    unsigned k1a, k1b, k2a, k2b;
    tf2x32(f0, f1, 0u, 0u, k1a, k1b);                 // split[0] -> uniform key
    tf2x32(f0, f1, 0u, 1u, k2a, k2b);                 // split[1] -> randint key
    unsigned ha, hb2, la, lb2;
    tf2x32(k2a, k2b, 0u, 0u, ha, hb2);                // randint higher-bits key
    tf2x32(k2a, k2b, 0u, 1u, la, lb2);                // randint lower-bits key
    keys[i][0] = k1a; keys[i][1] = k1b;
    keys[i][2] = ha;  keys[i][3] = hb2;
    keys[i][4] = la;  keys[i][5] = lb2;
  }

  for (int i = 0; i < 3; i++) {
    const float* cw = (const float*)d_in[1 + 4 * i];
    const float* cb = (const float*)d_in[2 + 4 * i];
    const float* gw = (const float*)d_in[3 + 4 * i];
    const float* gb = (const float*)d_in[4 + 4 * i];
    const float* in = (i == 0) ? x0 : p_xbuf;
    int Cin = (i == 0) ? 257 : 256;
    conv_kernel<<<dim3(3, 2, BB), 256>>>(in, cw, cb, p_conv, Cin);
    gn_stats<<<BB * 16, 128>>>(p_conv, p_mu, p_rsig);
    interp_meta<<<2, 256>>>(p_gi, p_lam, keys[i][0], keys[i][1], keys[i][2],
                            keys[i][3], keys[i][4], keys[i][5]);
    interp_apply<<<BB, 192>>>(p_conv, p_gi, p_lam, p_mu, p_rsig, gw, gb, p_xbuf);
  }
  xg_gemm<<<dim3(3, 2, BB), 256>>>(p_xbuf, (const float*)d_in[13],
                                   (const float*)d_in[17], (const float*)d_in[15],
                                   (const float*)d_in[16], (const float*)d_in[19],
                                   (const float*)d_in[20], p_xg);
  lstm_kernel<<<dim3(64, 2), 256>>>(p_xg, (const float*)d_in[14],
                                    (const float*)d_in[18], (float*)d_out);
}